// round 1
// baseline (speedup 1.0000x reference)
#include <cuda_runtime.h>
#include <cstdint>

#define BATCH 16
#define CCH   256
#define NPIX  1024
#define GROUPS 8

// ---------------- scratch (static device globals; no allocation) ----------------
__device__ float g_xn [BATCH * CCH * NPIX];            // 16 MB
__device__ float g_qkv[BATCH * 3 * CCH * NPIX];        // 48 MB
__device__ float g_s  [(size_t)BATCH * NPIX * NPIX];   // 64 MB
__device__ float g_o  [BATCH * CCH * NPIX];            // 16 MB

// ---------------- GroupNorm ----------------
// one block per (batch, group); group = 32 channels x 1024 pixels = 32768 contiguous floats
__global__ void groupnorm_k(const float* __restrict__ x,
                            const float* __restrict__ gamma,
                            const float* __restrict__ beta,
                            float* __restrict__ xn)
{
    const int GS = (CCH / GROUPS) * NPIX;   // 32768
    int bg = blockIdx.x;
    const float* xp = x + (size_t)bg * GS;
    float* op = xn + (size_t)bg * GS;

    float s = 0.f, s2 = 0.f;
    for (int i = threadIdx.x; i < GS; i += blockDim.x) {
        float v = xp[i];
        s += v; s2 += v * v;
    }
    __shared__ float sh0[8], sh1[8];
    #pragma unroll
    for (int o = 16; o > 0; o >>= 1) {
        s  += __shfl_xor_sync(0xffffffffu, s,  o);
        s2 += __shfl_xor_sync(0xffffffffu, s2, o);
    }
    int warp = threadIdx.x >> 5, lane = threadIdx.x & 31;
    if (lane == 0) { sh0[warp] = s; sh1[warp] = s2; }
    __syncthreads();
    if (warp == 0) {
        s  = (lane < 8) ? sh0[lane] : 0.f;
        s2 = (lane < 8) ? sh1[lane] : 0.f;
        #pragma unroll
        for (int o = 4; o > 0; o >>= 1) {
            s  += __shfl_xor_sync(0xffffffffu, s,  o);
            s2 += __shfl_xor_sync(0xffffffffu, s2, o);
        }
        if (lane == 0) { sh0[0] = s; sh1[0] = s2; }
    }
    __syncthreads();
    float mean = sh0[0] / GS;
    float var  = sh1[0] / GS - mean * mean;
    float rstd = rsqrtf(var + 1e-5f);
    int g = bg % GROUPS;
    for (int i = threadIdx.x; i < GS; i += blockDim.x) {
        int ch = g * (CCH / GROUPS) + (i >> 10);
        op[i] = (xp[i] - mean) * rstd * gamma[ch] + beta[ch];
    }
}

// ---------------- tiled SGEMM ----------------
// C[m,n] = alpha * sum_k A[m,k]*B[k,n] (+bias[m]) (+resid[m,n])
// TA==1: A stored as A[k*lda + m] ; TB==1: B stored as B[n*ldb + k]
// 64x64 tile, BK=16, 256 threads, 4x4 per thread. All dims divide tiles exactly.
template<int TA, int TB>
__global__ void gemm64_k(const float* __restrict__ A, const float* __restrict__ B,
                         float* __restrict__ Cmat, int M, int N, int K,
                         int lda, int ldb, int ldc,
                         long sA, long sB, long sC,
                         const float* __restrict__ bias,
                         const float* __restrict__ resid, long sR,
                         float alpha)
{
    __shared__ float As[16][65];
    __shared__ float Bs[16][65];
    A    += (size_t)blockIdx.z * sA;
    B    += (size_t)blockIdx.z * sB;
    Cmat += (size_t)blockIdx.z * sC;

    const int m0 = blockIdx.y * 64, n0 = blockIdx.x * 64;
    const int tid = threadIdx.x;
    const int tx = tid & 15, ty = tid >> 4;

    float acc[4][4] = {};

    for (int k0 = 0; k0 < K; k0 += 16) {
        if (TA == 0) {
            #pragma unroll
            for (int i = tid; i < 1024; i += 256) {
                int ml = i >> 4, kl = i & 15;
                As[kl][ml] = A[(size_t)(m0 + ml) * lda + k0 + kl];
            }
        } else {
            #pragma unroll
            for (int i = tid; i < 1024; i += 256) {
                int kl = i >> 6, ml = i & 63;
                As[kl][ml] = A[(size_t)(k0 + kl) * lda + m0 + ml];
            }
        }
        if (TB == 0) {
            #pragma unroll
            for (int i = tid; i < 1024; i += 256) {
                int kl = i >> 6, nl = i & 63;
                Bs[kl][nl] = B[(size_t)(k0 + kl) * ldb + n0 + nl];
            }
        } else {
            #pragma unroll
            for (int i = tid; i < 1024; i += 256) {
                int nl = i >> 4, kl = i & 15;
                Bs[kl][nl] = B[(size_t)(n0 + nl) * ldb + k0 + kl];
            }
        }
        __syncthreads();

        #pragma unroll
        for (int kk = 0; kk < 16; kk++) {
            float a[4], b[4];
            #pragma unroll
            for (int i = 0; i < 4; i++) a[i] = As[kk][ty + 16 * i];
            #pragma unroll
            for (int j = 0; j < 4; j++) b[j] = Bs[kk][tx + 16 * j];
            #pragma unroll
            for (int i = 0; i < 4; i++)
                #pragma unroll
                for (int j = 0; j < 4; j++)
                    acc[i][j] += a[i] * b[j];
        }
        __syncthreads();
    }

    #pragma unroll
    for (int i = 0; i < 4; i++) {
        int m = m0 + ty + 16 * i;
        float bv = bias ? bias[m] : 0.f;
        #pragma unroll
        for (int j = 0; j < 4; j++) {
            int n = n0 + tx + 16 * j;
            float v = alpha * acc[i][j] + bv;
            if (resid) v += resid[(size_t)blockIdx.z * sR + (size_t)m * ldc + n];
            Cmat[(size_t)m * ldc + n] = v;
        }
    }
}

// ---------------- row softmax over 1024 ----------------
__global__ void softmax_k(float* __restrict__ S)
{
    __shared__ float buf[NPIX];
    __shared__ float red[8];
    float* p = S + (size_t)blockIdx.x * NPIX;
    int tid = threadIdx.x;
    int warp = tid >> 5, lane = tid & 31;

    float m = -1e30f;
    for (int i = tid; i < NPIX; i += 256) {
        float v = p[i]; buf[i] = v; m = fmaxf(m, v);
    }
    #pragma unroll
    for (int o = 16; o > 0; o >>= 1) m = fmaxf(m, __shfl_xor_sync(0xffffffffu, m, o));
    if (lane == 0) red[warp] = m;
    __syncthreads();
    if (warp == 0) {
        float v = (lane < 8) ? red[lane] : -1e30f;
        #pragma unroll
        for (int o = 4; o > 0; o >>= 1) v = fmaxf(v, __shfl_xor_sync(0xffffffffu, v, o));
        if (lane == 0) red[0] = v;
    }
    __syncthreads();
    m = red[0];
    __syncthreads();

    float s = 0.f;
    for (int i = tid; i < NPIX; i += 256) {
        float e = __expf(buf[i] - m);
        buf[i] = e; s += e;
    }
    #pragma unroll
    for (int o = 16; o > 0; o >>= 1) s += __shfl_xor_sync(0xffffffffu, s, o);
    if (lane == 0) red[warp] = s;
    __syncthreads();
    if (warp == 0) {
        float v = (lane < 8) ? red[lane] : 0.f;
        #pragma unroll
        for (int o = 4; o > 0; o >>= 1) v += __shfl_xor_sync(0xffffffffu, v, o);
        if (lane == 0) red[0] = v;
    }
    __syncthreads();
    float inv = 1.f / red[0];
    for (int i = tid; i < NPIX; i += 256) p[i] = buf[i] * inv;
}

// ---------------- launch ----------------
extern "C" void kernel_launch(void* const* d_in, const int* in_sizes, int n_in,
                              void* d_out, int out_size)
{
    const float* x      = (const float*)d_in[0];
    const float* gamma  = (const float*)d_in[1];
    const float* beta   = (const float*)d_in[2];
    const float* w_qkv  = (const float*)d_in[3];
    const float* b_qkv  = (const float*)d_in[4];
    const float* w_proj = (const float*)d_in[5];
    const float* b_proj = (const float*)d_in[6];
    float* out = (float*)d_out;

    float *xn, *qkv, *s, *o;
    cudaGetSymbolAddress((void**)&xn,  g_xn);
    cudaGetSymbolAddress((void**)&qkv, g_qkv);
    cudaGetSymbolAddress((void**)&s,   g_s);
    cudaGetSymbolAddress((void**)&o,   g_o);

    // 1) GroupNorm
    groupnorm_k<<<BATCH * GROUPS, 256>>>(x, gamma, beta, xn);

    // 2) QKV: [768,256] x [256,1024] per batch (+bias)
    gemm64_k<0, 0><<<dim3(NPIX / 64, (3 * CCH) / 64, BATCH), 256>>>(
        w_qkv, xn, qkv, 3 * CCH, NPIX, CCH,
        CCH, NPIX, NPIX,
        0L, (long)CCH * NPIX, (long)3 * CCH * NPIX,
        b_qkv, nullptr, 0L, 1.f);

    // 3) scores S[n,m] = (1/16) * sum_c q[c,n] k[c,m]   (TA=1: A stored [k][m])
    gemm64_k<1, 0><<<dim3(NPIX / 64, NPIX / 64, BATCH), 256>>>(
        qkv, qkv + CCH * NPIX, s, NPIX, NPIX, CCH,
        NPIX, NPIX, NPIX,
        (long)3 * CCH * NPIX, (long)3 * CCH * NPIX, (long)NPIX * NPIX,
        nullptr, nullptr, 0L, 0.0625f);

    // 4) softmax along m
    softmax_k<<<BATCH * NPIX, 256>>>(s);

    // 5) O[c,n] = sum_m v[c,m] P[n,m]   (TB=1: B stored [n][k])
    gemm64_k<0, 1><<<dim3(NPIX / 64, CCH / 64, BATCH), 256>>>(
        qkv + 2 * CCH * NPIX, s, o, CCH, NPIX, NPIX,
        NPIX, NPIX, NPIX,
        (long)3 * CCH * NPIX, (long)NPIX * NPIX, (long)CCH * NPIX,
        nullptr, nullptr, 0L, 1.f);

    // 6) proj + bias + residual
    gemm64_k<0, 0><<<dim3(NPIX / 64, CCH / 64, BATCH), 256>>>(
        w_proj, o, out, CCH, NPIX, CCH,
        CCH, NPIX, NPIX,
        0L, (long)CCH * NPIX, (long)CCH * NPIX,
        b_proj, x, (long)CCH * NPIX, 1.f);
}

// round 2
// speedup vs baseline: 3.9164x; 3.9164x over previous
#include <cuda_runtime.h>
#include <cstdint>

#define BATCH 16
#define CCH   256
#define NPIX  1024
#define GROUPS 8

// ---------------- scratch (static device globals; no allocation) ----------------
__device__ float g_xn [BATCH * CCH * NPIX];            // 16 MB
__device__ float g_qkv[BATCH * 3 * CCH * NPIX];        // 48 MB
__device__ float g_s  [(size_t)BATCH * NPIX * NPIX];   // 64 MB
__device__ float g_o  [BATCH * CCH * NPIX];            // 16 MB
__device__ float g_wq [3 * CCH * CCH];                 // tf32-rounded w_qkv
__device__ float g_wp [CCH * CCH];                     // tf32-rounded w_proj

// ---------------- helpers ----------------
__device__ __forceinline__ float tf32r(float x) {
    uint32_t u;
    asm("cvt.rna.tf32.f32 %0, %1;" : "=r"(u) : "f"(x));
    return __uint_as_float(u);
}
__device__ __forceinline__ void cpa16(uint32_t dst, const void* src) {
    asm volatile("cp.async.cg.shared.global [%0], [%1], 16;" :: "r"(dst), "l"(src));
}
__device__ __forceinline__ void cp_commit() {
    asm volatile("cp.async.commit_group;");
}
template<int N>
__device__ __forceinline__ void cp_wait() {
    asm volatile("cp.async.wait_group %0;" :: "n"(N));
}
__device__ __forceinline__ void mma_tf32(float& c0, float& c1, float& c2, float& c3,
                                         uint32_t a0, uint32_t a1, uint32_t a2, uint32_t a3,
                                         uint32_t b0, uint32_t b1) {
    asm volatile(
        "mma.sync.aligned.m16n8k8.row.col.f32.tf32.tf32.f32 "
        "{%0,%1,%2,%3}, {%4,%5,%6,%7}, {%8,%9}, {%0,%1,%2,%3};"
        : "+f"(c0), "+f"(c1), "+f"(c2), "+f"(c3)
        : "r"(a0), "r"(a1), "r"(a2), "r"(a3), "r"(b0), "r"(b1));
}

// ---------------- tf32 rounding copy (weights) ----------------
__global__ void round_copy_k(const float* __restrict__ src, float* __restrict__ dst, int n) {
    int i = blockIdx.x * blockDim.x + threadIdx.x;
    if (i < n) dst[i] = tf32r(src[i]);
}

// ---------------- GroupNorm (outputs tf32-rounded) ----------------
__global__ void groupnorm_k(const float* __restrict__ x,
                            const float* __restrict__ gamma,
                            const float* __restrict__ beta,
                            float* __restrict__ xn)
{
    const int GS = (CCH / GROUPS) * NPIX;   // 32768
    int bg = blockIdx.x;
    const float* xp = x + (size_t)bg * GS;
    float* op = xn + (size_t)bg * GS;

    float s = 0.f, s2 = 0.f;
    for (int i = threadIdx.x; i < GS; i += blockDim.x) {
        float v = xp[i];
        s += v; s2 += v * v;
    }
    __shared__ float sh0[8], sh1[8];
    #pragma unroll
    for (int o = 16; o > 0; o >>= 1) {
        s  += __shfl_xor_sync(0xffffffffu, s,  o);
        s2 += __shfl_xor_sync(0xffffffffu, s2, o);
    }
    int warp = threadIdx.x >> 5, lane = threadIdx.x & 31;
    if (lane == 0) { sh0[warp] = s; sh1[warp] = s2; }
    __syncthreads();
    if (warp == 0) {
        s  = (lane < 8) ? sh0[lane] : 0.f;
        s2 = (lane < 8) ? sh1[lane] : 0.f;
        #pragma unroll
        for (int o = 4; o > 0; o >>= 1) {
            s  += __shfl_xor_sync(0xffffffffu, s,  o);
            s2 += __shfl_xor_sync(0xffffffffu, s2, o);
        }
        if (lane == 0) { sh0[0] = s; sh1[0] = s2; }
    }
    __syncthreads();
    float mean = sh0[0] / GS;
    float var  = sh1[0] / GS - mean * mean;
    float rstd = rsqrtf(var + 1e-5f);
    int g = bg % GROUPS;
    for (int i = threadIdx.x; i < GS; i += blockDim.x) {
        int ch = g * (CCH / GROUPS) + (i >> 10);
        op[i] = tf32r((xp[i] - mean) * rstd * gamma[ch] + beta[ch]);
    }
}

// ---------------- TF32 tensor-core GEMM ----------------
// C[m,n] = alpha * sum_k A[m,k]*B[k,n] (+bias[m]) (+resid) ; optional tf32-round of output
// TA==1: A stored as A[k*lda + m] ; TB==1: B stored as B[n*ldb + k]
// BM=BN=128, BK=32, 256 threads (8 warps of 64x32), cp.async 2-stage pipeline.
template<int TA, int TB, int ROUND>
__global__ void __launch_bounds__(256, 2)
gemm_tc(const float* __restrict__ A, const float* __restrict__ B,
        float* __restrict__ Cmat, int K,
        int lda, int ldb, int ldc,
        long sA, long sB, long sC,
        const float* __restrict__ bias,
        const float* __restrict__ resid, long sR,
        float alpha)
{
    extern __shared__ uint32_t sh[];
    constexpr int ASTG = (TA == 0) ? 128 * 36 : 32 * 132;
    constexpr int BSTG = (TB == 0) ? 32 * 132 : 128 * 36;
    uint32_t* As = sh;
    uint32_t* Bs = sh + 2 * ASTG;

    A    += (size_t)blockIdx.z * sA;
    B    += (size_t)blockIdx.z * sB;
    Cmat += (size_t)blockIdx.z * sC;

    const int m0 = blockIdx.y * 128, n0 = blockIdx.x * 128;
    const int tid = threadIdx.x;
    const int lane = tid & 31, wid = tid >> 5;
    const int warp_m = wid & 1, warp_n = wid >> 1;   // 2 x 4 warps
    const int g = lane >> 2, tr = lane & 3;

    float c[4][4][4];
    #pragma unroll
    for (int i = 0; i < 4; i++)
        #pragma unroll
        for (int j = 0; j < 4; j++)
            #pragma unroll
            for (int t = 0; t < 4; t++) c[i][j][t] = 0.f;

    // per-thread copy coordinates
    const int cm8 = tid >> 3, cq8 = tid & 7;    // 128-row x 8-f4 pattern
    const int ck32 = tid >> 5, cq32 = tid & 31; // 32-row x 32-f4 pattern (fits 256 thr? no: 32*32=1024 /256 = 4 passes below)

    auto issueA = [&](int k0, int b) {
        uint32_t base = (uint32_t)__cvta_generic_to_shared(As + b * ASTG);
        if (TA == 0) {
            #pragma unroll
            for (int p = 0; p < 4; p++) {
                int m = cm8 + 32 * p;   // wrong stride? cm8 in 0..31 only
                // cm8 spans 0..31 (tid>>3), cover 128 rows via +32*p
                cpa16(base + (uint32_t)((m * 36 + cq8 * 4) * 4),
                      &A[(size_t)(m0 + m) * lda + k0 + cq8 * 4]);
            }
        } else {
            #pragma unroll
            for (int p = 0; p < 4; p++) {
                int idx = tid + 256 * p;          // 0..1023
                int k = idx >> 5, q = idx & 31;
                cpa16(base + (uint32_t)((k * 132 + q * 4) * 4),
                      &A[(size_t)(k0 + k) * lda + m0 + q * 4]);
            }
        }
    };
    auto issueB = [&](int k0, int b) {
        uint32_t base = (uint32_t)__cvta_generic_to_shared(Bs + b * BSTG);
        if (TB == 0) {
            #pragma unroll
            for (int p = 0; p < 4; p++) {
                int idx = tid + 256 * p;
                int k = idx >> 5, q = idx & 31;
                cpa16(base + (uint32_t)((k * 132 + q * 4) * 4),
                      &B[(size_t)(k0 + k) * ldb + n0 + q * 4]);
            }
        } else {
            #pragma unroll
            for (int p = 0; p < 4; p++) {
                int n = cm8 + 32 * p;
                cpa16(base + (uint32_t)((n * 36 + cq8 * 4) * 4),
                      &B[(size_t)(n0 + n) * ldb + k0 + cq8 * 4]);
            }
        }
    };

    const int kt = K >> 5;   // K / 32, always >= 2 here

    issueA(0, 0); issueB(0, 0); cp_commit();
    issueA(32, 1); issueB(32, 1); cp_commit();
    cp_wait<1>();
    __syncthreads();

    for (int it = 0; it < kt; it++) {
        const int b = it & 1;
        const uint32_t* Ab = As + b * ASTG;
        const uint32_t* Bb = Bs + b * BSTG;

        #pragma unroll
        for (int kk = 0; kk < 4; kk++) {
            const int kidx = kk * 8 + tr;
            uint32_t af[4][4];
            #pragma unroll
            for (int mf = 0; mf < 4; mf++) {
                int rm = warp_m * 64 + mf * 16 + g;
                if (TA == 0) {
                    af[mf][0] = Ab[rm * 36 + kidx];
                    af[mf][1] = Ab[(rm + 8) * 36 + kidx];
                    af[mf][2] = Ab[rm * 36 + kidx + 4];
                    af[mf][3] = Ab[(rm + 8) * 36 + kidx + 4];
                } else {
                    af[mf][0] = Ab[kidx * 132 + rm];
                    af[mf][1] = Ab[kidx * 132 + rm + 8];
                    af[mf][2] = Ab[(kidx + 4) * 132 + rm];
                    af[mf][3] = Ab[(kidx + 4) * 132 + rm + 8];
                }
            }
            uint32_t bf[4][2];
            #pragma unroll
            for (int nf = 0; nf < 4; nf++) {
                int cn = warp_n * 32 + nf * 8 + g;
                if (TB == 0) {
                    bf[nf][0] = Bb[kidx * 132 + cn];
                    bf[nf][1] = Bb[(kidx + 4) * 132 + cn];
                } else {
                    bf[nf][0] = Bb[cn * 36 + kidx];
                    bf[nf][1] = Bb[cn * 36 + kidx + 4];
                }
            }
            #pragma unroll
            for (int mf = 0; mf < 4; mf++)
                #pragma unroll
                for (int nf = 0; nf < 4; nf++)
                    mma_tf32(c[mf][nf][0], c[mf][nf][1], c[mf][nf][2], c[mf][nf][3],
                             af[mf][0], af[mf][1], af[mf][2], af[mf][3],
                             bf[nf][0], bf[nf][1]);
        }
        __syncthreads();
        if (it + 2 < kt) {
            issueA((it + 2) * 32, b); issueB((it + 2) * 32, b); cp_commit();
            cp_wait<1>();
        } else {
            cp_wait<0>();
        }
        __syncthreads();
    }

    // epilogue
    #pragma unroll
    for (int mf = 0; mf < 4; mf++) {
        int r0 = m0 + warp_m * 64 + mf * 16 + g;
        float bv0 = bias ? bias[r0] : 0.f;
        float bv1 = bias ? bias[r0 + 8] : 0.f;
        #pragma unroll
        for (int nf = 0; nf < 4; nf++) {
            int cc = n0 + warp_n * 32 + nf * 8 + 2 * tr;
            float v0 = alpha * c[mf][nf][0] + bv0;
            float v1 = alpha * c[mf][nf][1] + bv0;
            float v2 = alpha * c[mf][nf][2] + bv1;
            float v3 = alpha * c[mf][nf][3] + bv1;
            if (resid) {
                const float* rp = resid + (size_t)blockIdx.z * sR;
                v0 += rp[(size_t)r0 * ldc + cc];
                v1 += rp[(size_t)r0 * ldc + cc + 1];
                v2 += rp[(size_t)(r0 + 8) * ldc + cc];
                v3 += rp[(size_t)(r0 + 8) * ldc + cc + 1];
            }
            if (ROUND) { v0 = tf32r(v0); v1 = tf32r(v1); v2 = tf32r(v2); v3 = tf32r(v3); }
            *(float2*)&Cmat[(size_t)r0 * ldc + cc] = make_float2(v0, v1);
            *(float2*)&Cmat[(size_t)(r0 + 8) * ldc + cc] = make_float2(v2, v3);
        }
    }
}

// ---------------- row softmax over 1024 (outputs tf32-rounded) ----------------
__global__ void softmax_k(float* __restrict__ S)
{
    __shared__ float buf[NPIX];
    __shared__ float red[8];
    float* p = S + (size_t)blockIdx.x * NPIX;
    int tid = threadIdx.x;
    int warp = tid >> 5, lane = tid & 31;

    float m = -1e30f;
    for (int i = tid; i < NPIX; i += 256) {
        float v = p[i]; buf[i] = v; m = fmaxf(m, v);
    }
    #pragma unroll
    for (int o = 16; o > 0; o >>= 1) m = fmaxf(m, __shfl_xor_sync(0xffffffffu, m, o));
    if (lane == 0) red[warp] = m;
    __syncthreads();
    if (warp == 0) {
        float v = (lane < 8) ? red[lane] : -1e30f;
        #pragma unroll
        for (int o = 4; o > 0; o >>= 1) v = fmaxf(v, __shfl_xor_sync(0xffffffffu, v, o));
        if (lane == 0) red[0] = v;
    }
    __syncthreads();
    m = red[0];
    __syncthreads();

    float s = 0.f;
    for (int i = tid; i < NPIX; i += 256) {
        float e = __expf(buf[i] - m);
        buf[i] = e; s += e;
    }
    #pragma unroll
    for (int o = 16; o > 0; o >>= 1) s += __shfl_xor_sync(0xffffffffu, s, o);
    if (lane == 0) red[warp] = s;
    __syncthreads();
    if (warp == 0) {
        float v = (lane < 8) ? red[lane] : 0.f;
        #pragma unroll
        for (int o = 4; o > 0; o >>= 1) v += __shfl_xor_sync(0xffffffffu, v, o);
        if (lane == 0) red[0] = v;
    }
    __syncthreads();
    float inv = 1.f / red[0];
    for (int i = tid; i < NPIX; i += 256) p[i] = tf32r(buf[i] * inv);
}

// ---------------- launch ----------------
extern "C" void kernel_launch(void* const* d_in, const int* in_sizes, int n_in,
                              void* d_out, int out_size)
{
    const float* x      = (const float*)d_in[0];
    const float* gamma  = (const float*)d_in[1];
    const float* beta   = (const float*)d_in[2];
    const float* w_qkv  = (const float*)d_in[3];
    const float* b_qkv  = (const float*)d_in[4];
    const float* w_proj = (const float*)d_in[5];
    const float* b_proj = (const float*)d_in[6];
    float* out = (float*)d_out;

    float *xn, *qkv, *s, *o, *wq, *wp;
    cudaGetSymbolAddress((void**)&xn,  g_xn);
    cudaGetSymbolAddress((void**)&qkv, g_qkv);
    cudaGetSymbolAddress((void**)&s,   g_s);
    cudaGetSymbolAddress((void**)&o,   g_o);
    cudaGetSymbolAddress((void**)&wq,  g_wq);
    cudaGetSymbolAddress((void**)&wp,  g_wp);

    // dynamic smem sizes per instantiation
    const int SM_00 = (128 * 36 + 32 * 132) * 2 * 4;   // 70656
    const int SM_10 = (32 * 132 + 32 * 132) * 2 * 4;   // 67584
    const int SM_01 = (128 * 36 + 128 * 36) * 2 * 4;   // 73728
    cudaFuncSetAttribute(gemm_tc<0,0,1>, cudaFuncAttributeMaxDynamicSharedMemorySize, SM_00);
    cudaFuncSetAttribute(gemm_tc<0,0,0>, cudaFuncAttributeMaxDynamicSharedMemorySize, SM_00);
    cudaFuncSetAttribute(gemm_tc<1,0,0>, cudaFuncAttributeMaxDynamicSharedMemorySize, SM_10);
    cudaFuncSetAttribute(gemm_tc<0,1,1>, cudaFuncAttributeMaxDynamicSharedMemorySize, SM_01);

    // 0) round weights to tf32 grid
    round_copy_k<<<(3 * CCH * CCH + 255) / 256, 256>>>(w_qkv, wq, 3 * CCH * CCH);
    round_copy_k<<<(CCH * CCH + 255) / 256, 256>>>(w_proj, wp, CCH * CCH);

    // 1) GroupNorm (tf32-rounded output)
    groupnorm_k<<<BATCH * GROUPS, 256>>>(x, gamma, beta, xn);

    // 2) QKV: [768,256] x [256,1024] per batch (+bias), rounded output
    gemm_tc<0,0,1><<<dim3(NPIX / 128, (3 * CCH) / 128, BATCH), 256, SM_00>>>(
        wq, xn, qkv, CCH,
        CCH, NPIX, NPIX,
        0L, (long)CCH * NPIX, (long)3 * CCH * NPIX,
        b_qkv, nullptr, 0L, 1.f);

    // 3) scores S[n,m] = (1/16) * sum_c q[c,n] k[c,m]
    gemm_tc<1,0,0><<<dim3(NPIX / 128, NPIX / 128, BATCH), 256, SM_10>>>(
        qkv, qkv + CCH * NPIX, s, CCH,
        NPIX, NPIX, NPIX,
        (long)3 * CCH * NPIX, (long)3 * CCH * NPIX, (long)NPIX * NPIX,
        nullptr, nullptr, 0L, 0.0625f);

    // 4) softmax along m (tf32-rounded output)
    softmax_k<<<BATCH * NPIX, 256>>>(s);

    // 5) O[c,n] = sum_m v[c,m] P[n,m], rounded output
    gemm_tc<0,1,1><<<dim3(NPIX / 128, CCH / 128, BATCH), 256, SM_01>>>(
        qkv + 2 * CCH * NPIX, s, o, NPIX,
        NPIX, NPIX, NPIX,
        (long)3 * CCH * NPIX, (long)NPIX * NPIX, (long)CCH * NPIX,
        nullptr, nullptr, 0L, 1.f);

    // 6) proj + bias + residual (exact fp32 epilogue)
    gemm_tc<0,0,0><<<dim3(NPIX / 128, CCH / 128, BATCH), 256, SM_00>>>(
        wp, o, out, CCH,
        CCH, NPIX, NPIX,
        0L, (long)CCH * NPIX, (long)CCH * NPIX,
        b_proj, x, (long)CCH * NPIX, 1.f);
}

// round 5
// speedup vs baseline: 6.7525x; 1.7242x over previous
#include <cuda_runtime.h>
#include <cuda_fp16.h>
#include <cstdint>

#define BATCH 16
#define CCH   256
#define NPIX  1024

// ---------------- scratch (static device globals; no allocation) ----------------
__device__ __align__(128) __half g_xnT[BATCH * NPIX * CCH];           //  8 MB [b][n][c]
__device__ __align__(128) __half g_qkT[BATCH * NPIX * 3 * CCH];       // 24 MB [b][n][o]
__device__ __align__(128) __half g_vT [BATCH * CCH * NPIX];           //  8 MB [b][c][m]
__device__ __align__(128) __half g_E  [(size_t)BATCH * NPIX * NPIX];  // 32 MB [b][n][m]
__device__ __align__(128) __half g_O  [BATCH * NPIX * CCH];           //  8 MB [b][n][c]
__device__ __align__(128) float  g_rs [BATCH * NPIX];
__device__ __align__(128) __half g_wq [3 * CCH * CCH];
__device__ __align__(128) __half g_wp [CCH * CCH];

// ---------------- helpers ----------------
__device__ __forceinline__ void cpa16(uint32_t dst, const void* src) {
    asm volatile("cp.async.cg.shared.global [%0], [%1], 16;" :: "r"(dst), "l"(src));
}
__device__ __forceinline__ void cp_commit() { asm volatile("cp.async.commit_group;"); }
template<int N> __device__ __forceinline__ void cp_wait() { asm volatile("cp.async.wait_group %0;" :: "n"(N)); }

__device__ __forceinline__ void mma_f16(float& c0, float& c1, float& c2, float& c3,
                                        uint32_t a0, uint32_t a1, uint32_t a2, uint32_t a3,
                                        uint32_t b0, uint32_t b1) {
    asm volatile(
        "mma.sync.aligned.m16n8k16.row.col.f32.f16.f16.f32 "
        "{%0,%1,%2,%3}, {%4,%5,%6,%7}, {%8,%9}, {%0,%1,%2,%3};"
        : "+f"(c0), "+f"(c1), "+f"(c2), "+f"(c3)
        : "r"(a0), "r"(a1), "r"(a2), "r"(a3), "r"(b0), "r"(b1));
}

// ---------------- prep: fp16 weights + zero rowsums ----------------
__global__ void prep_k(const float* __restrict__ wq, const float* __restrict__ wp,
                       __half* __restrict__ owq, __half* __restrict__ owp,
                       float* __restrict__ rs)
{
    int i = blockIdx.x * 256 + threadIdx.x;
    if (i < 3 * CCH * CCH) owq[i] = __float2half(wq[i]);
    if (i < CCH * CCH)     owp[i] = __float2half(wp[i]);
    if (i < BATCH * NPIX)  rs[i]  = 0.f;
}

// ---------------- GroupNorm -> transposed fp16 xnT[b][pix][chan] ----------------
__global__ void groupnorm_k(const float* __restrict__ x, const float* __restrict__ gamma,
                            const float* __restrict__ beta, __half* __restrict__ xnT)
{
    __shared__ float smT[32][65];
    __shared__ float red0[8], red1[8];
    const int bg = blockIdx.x, b = bg >> 3, g = bg & 7;
    const float* xp = x + (size_t)bg * 32768;
    const int tid = threadIdx.x, lane = tid & 31, warp = tid >> 5;

    float s = 0.f, s2 = 0.f;
    for (int i = tid; i < 32768; i += 256) { float v = xp[i]; s += v; s2 += v * v; }
    #pragma unroll
    for (int o = 16; o > 0; o >>= 1) {
        s  += __shfl_xor_sync(0xffffffffu, s,  o);
        s2 += __shfl_xor_sync(0xffffffffu, s2, o);
    }
    if (lane == 0) { red0[warp] = s; red1[warp] = s2; }
    __syncthreads();
    if (warp == 0) {
        s  = (lane < 8) ? red0[lane] : 0.f;
        s2 = (lane < 8) ? red1[lane] : 0.f;
        #pragma unroll
        for (int o = 4; o > 0; o >>= 1) {
            s  += __shfl_xor_sync(0xffffffffu, s,  o);
            s2 += __shfl_xor_sync(0xffffffffu, s2, o);
        }
        if (lane == 0) { red0[0] = s; red1[0] = s2; }
    }
    __syncthreads();
    float mean = red0[0] * (1.f / 32768.f);
    float var  = red1[0] * (1.f / 32768.f) - mean * mean;
    float rstd = rsqrtf(var + 1e-5f);

    const int p = tid >> 2, cq = (tid & 3) * 8;
    float gm[8], bt[8];
    #pragma unroll
    for (int j = 0; j < 8; j++) {
        float gj = gamma[g * 32 + cq + j] * rstd;
        gm[j] = gj;
        bt[j] = beta[g * 32 + cq + j] - mean * gj;
    }
    for (int tp = 0; tp < 1024; tp += 64) {
        __syncthreads();
        #pragma unroll
        for (int i = 0; i < 8; i++) {
            int idx = tid + 256 * i;
            int c = idx >> 6, pp = idx & 63;
            smT[c][pp] = xp[c * 1024 + tp + pp];
        }
        __syncthreads();
        uint32_t pk[4];
        #pragma unroll
        for (int j = 0; j < 4; j++) {
            float v0 = smT[cq + 2 * j][p]     * gm[2 * j]     + bt[2 * j];
            float v1 = smT[cq + 2 * j + 1][p] * gm[2 * j + 1] + bt[2 * j + 1];
            __half2 h = __floats2half2_rn(v0, v1);
            pk[j] = *(uint32_t*)&h;
        }
        *(uint4*)&xnT[((size_t)b * NPIX + tp + p) * CCH + g * 32 + cq] = *(uint4*)pk;
    }
}

// ---------------- v transpose: qkT[b][m][512+c] -> vT[b][c][m] ----------------
__global__ void vtrans_k(const __half* __restrict__ qkT, __half* __restrict__ vT)
{
    __shared__ __half t[32][33];
    int b = blockIdx.z, m0 = blockIdx.x * 32, c0 = blockIdx.y * 32;
    int tx = threadIdx.x & 31, ty = threadIdx.x >> 5;
    const __half* src = qkT + (size_t)b * NPIX * 768 + 512 + c0;
    #pragma unroll
    for (int i = 0; i < 4; i++)
        t[ty + 8 * i][tx] = src[(size_t)(m0 + ty + 8 * i) * 768 + tx];
    __syncthreads();
    __half* dst = vT + (size_t)b * CCH * NPIX + (size_t)c0 * NPIX + m0;
    #pragma unroll
    for (int i = 0; i < 4; i++)
        dst[(size_t)(ty + 8 * i) * NPIX + tx] = t[tx][ty + 8 * i];
}

// ---------------- FP16 tensor-core GEMM: D[m,n] = sum_k A[m,k]*B[n,k] ----------------
// EPI: 0 = +bias[col] -> fp16 ; 1 = exp(alpha*d) + rowsum atomic -> fp16 ;
//      2 = d / rowsum[row] -> fp16 ; 3 = d + bias[row] + resid -> fp32
// BM=BN=128, BK=32 (16 half2 pairs), 256 threads (8 warps of 64x32), 2-stage cp.async.
template<int EPI>
__global__ void __launch_bounds__(256, 2)
gemm_h(const __half* __restrict__ A, const __half* __restrict__ B,
       void* __restrict__ Cv, int K, int lda, int ldb, int ldc,
       long sA, long sB, long sC,
       const float* __restrict__ bias, const float* __restrict__ resid, long sR,
       float* __restrict__ rowsum, float alpha)
{
    __shared__ uint32_t As[2][128][20];   // [stage][row][k-pair(16)+pad]
    __shared__ uint32_t Bs[2][128][20];

    const int z = blockIdx.z;
    A += (size_t)z * sA;
    B += (size_t)z * sB;

    const int m0 = blockIdx.y * 128, n0 = blockIdx.x * 128;
    const int tid = threadIdx.x, lane = tid & 31, wid = tid >> 5;
    const int warp_m = wid & 1, warp_n = wid >> 1;       // 2 x 4 warps
    const int g = lane >> 2, tr = lane & 3;

    float c[4][4][4];
    #pragma unroll
    for (int i = 0; i < 4; i++)
        #pragma unroll
        for (int j = 0; j < 4; j++)
            #pragma unroll
            for (int t = 0; t < 4; t++) c[i][j][t] = 0.f;

    const int crow = tid >> 2, cq = tid & 3;   // 64 rows per 256-thread pass? no: row=tid>>2 in 0..63

    auto loadA = [&](int s, int k0) {
        #pragma unroll
        for (int p = 0; p < 2; p++) {
            int row = crow + 64 * p;
            uint32_t dst = (uint32_t)__cvta_generic_to_shared(&As[s][row][cq * 4]);
            cpa16(dst, A + (size_t)(m0 + row) * lda + k0 + cq * 8);
        }
    };
    auto loadB = [&](int s, int k0) {
        #pragma unroll
        for (int p = 0; p < 2; p++) {
            int row = crow + 64 * p;
            uint32_t dst = (uint32_t)__cvta_generic_to_shared(&Bs[s][row][cq * 4]);
            cpa16(dst, B + (size_t)(n0 + row) * ldb + k0 + cq * 8);
        }
    };

    const int kt = K >> 5;   // K/32 >= 2 always here

    loadA(0, 0);  loadB(0, 0);  cp_commit();
    loadA(1, 32); loadB(1, 32); cp_commit();
    cp_wait<1>();
    __syncthreads();

    for (int it = 0; it < kt; it++) {
        const int s = it & 1;
        #pragma unroll
        for (int kk = 0; kk < 2; kk++) {
            const int kidx = kk * 8 + tr;
            uint32_t af[4][4];
            #pragma unroll
            for (int mf = 0; mf < 4; mf++) {
                int rm = warp_m * 64 + mf * 16 + g;
                af[mf][0] = As[s][rm][kidx];
                af[mf][1] = As[s][rm + 8][kidx];
                af[mf][2] = As[s][rm][kidx + 4];
                af[mf][3] = As[s][rm + 8][kidx + 4];
            }
            uint32_t bf[4][2];
            #pragma unroll
            for (int nf = 0; nf < 4; nf++) {
                int cn = warp_n * 32 + nf * 8 + g;
                bf[nf][0] = Bs[s][cn][kidx];
                bf[nf][1] = Bs[s][cn][kidx + 4];
            }
            #pragma unroll
            for (int mf = 0; mf < 4; mf++)
                #pragma unroll
                for (int nf = 0; nf < 4; nf++)
                    mma_f16(c[mf][nf][0], c[mf][nf][1], c[mf][nf][2], c[mf][nf][3],
                            af[mf][0], af[mf][1], af[mf][2], af[mf][3],
                            bf[nf][0], bf[nf][1]);
        }
        __syncthreads();
        if (it + 2 < kt) {
            loadA(s, (it + 2) * 32); loadB(s, (it + 2) * 32); cp_commit();
            cp_wait<1>();
        } else {
            cp_wait<0>();
        }
        __syncthreads();
    }

    // ---------------- epilogue ----------------
    #pragma unroll
    for (int mf = 0; mf < 4; mf++) {
        const int r0 = m0 + warp_m * 64 + mf * 16 + g;
        const int r1 = r0 + 8;
        float add0 = 0.f, add1 = 0.f, mul0 = 1.f, mul1 = 1.f;
        if (EPI == 3) { add0 = bias[r0]; add1 = bias[r1]; }
        if (EPI == 2) {
            mul0 = 1.f / rowsum[z * NPIX + r0];
            mul1 = 1.f / rowsum[z * NPIX + r1];
        }
        float rsum0 = 0.f, rsum1 = 0.f;
        #pragma unroll
        for (int nf = 0; nf < 4; nf++) {
            const int cc = n0 + warp_n * 32 + nf * 8 + 2 * tr;
            float v0 = c[mf][nf][0], v1 = c[mf][nf][1];
            float v2 = c[mf][nf][2], v3 = c[mf][nf][3];
            if (EPI == 0) {
                v0 += bias[cc]; v1 += bias[cc + 1];
                v2 += bias[cc]; v3 += bias[cc + 1];
            }
            if (EPI == 1) {
                v0 = __expf(v0 * alpha); v1 = __expf(v1 * alpha);
                v2 = __expf(v2 * alpha); v3 = __expf(v3 * alpha);
                rsum0 += v0 + v1; rsum1 += v2 + v3;
            }
            if (EPI == 2) { v0 *= mul0; v1 *= mul0; v2 *= mul1; v3 *= mul1; }
            if (EPI != 3) {
                __half* Ch = (__half*)Cv + (size_t)z * sC;
                __half2 h01 = __floats2half2_rn(v0, v1);
                __half2 h23 = __floats2half2_rn(v2, v3);
                *(__half2*)&Ch[(size_t)r0 * ldc + cc] = h01;
                *(__half2*)&Ch[(size_t)r1 * ldc + cc] = h23;
            } else {
                float* Cf = (float*)Cv + (size_t)z * sC;
                const float* Rp = resid + (size_t)z * sR;
                float2 o0 = make_float2(v0 + add0 + Rp[(size_t)r0 * ldc + cc],
                                        v1 + add0 + Rp[(size_t)r0 * ldc + cc + 1]);
                float2 o1 = make_float2(v2 + add1 + Rp[(size_t)r1 * ldc + cc],
                                        v3 + add1 + Rp[(size_t)r1 * ldc + cc + 1]);
                *(float2*)&Cf[(size_t)r0 * ldc + cc] = o0;
                *(float2*)&Cf[(size_t)r1 * ldc + cc] = o1;
            }
        }
        if (EPI == 1) {
            rsum0 += __shfl_xor_sync(0xffffffffu, rsum0, 1);
            rsum0 += __shfl_xor_sync(0xffffffffu, rsum0, 2);
            rsum1 += __shfl_xor_sync(0xffffffffu, rsum1, 1);
            rsum1 += __shfl_xor_sync(0xffffffffu, rsum1, 2);
            if (tr == 0) {
                atomicAdd(&rowsum[z * NPIX + r0], rsum0);
                atomicAdd(&rowsum[z * NPIX + r1], rsum1);
            }
        }
    }
}

// ---------------- launch ----------------
extern "C" void kernel_launch(void* const* d_in, const int* in_sizes, int n_in,
                              void* d_out, int out_size)
{
    const float* x      = (const float*)d_in[0];
    const float* gamma  = (const float*)d_in[1];
    const float* beta   = (const float*)d_in[2];
    const float* w_qkv  = (const float*)d_in[3];
    const float* b_qkv  = (const float*)d_in[4];
    const float* w_proj = (const float*)d_in[5];
    const float* b_proj = (const float*)d_in[6];
    float* out = (float*)d_out;

    __half *xnT, *qkT, *vT, *E, *O, *wq, *wp;
    float* rs;
    cudaGetSymbolAddress((void**)&xnT, g_xnT);
    cudaGetSymbolAddress((void**)&qkT, g_qkT);
    cudaGetSymbolAddress((void**)&vT,  g_vT);
    cudaGetSymbolAddress((void**)&E,   g_E);
    cudaGetSymbolAddress((void**)&O,   g_O);
    cudaGetSymbolAddress((void**)&wq,  g_wq);
    cudaGetSymbolAddress((void**)&wp,  g_wp);
    cudaGetSymbolAddress((void**)&rs,  g_rs);

    // 0) fp16 weights + zero rowsums
    prep_k<<<(3 * CCH * CCH + 255) / 256, 256>>>(w_qkv, w_proj, wq, wp, rs);

    // 1) GroupNorm -> xnT [b][n][c] fp16
    groupnorm_k<<<BATCH * 8, 256>>>(x, gamma, beta, xnT);

    // 2) QKV: D[n,o] = sum_c xnT[n,c]*Wqkv[o,c] + b[o] -> qkT fp16
    gemm_h<0><<<dim3(768 / 128, NPIX / 128, BATCH), 256>>>(
        xnT, wq, qkT, CCH, CCH, CCH, 768,
        (long)NPIX * CCH, 0L, (long)NPIX * 768,
        b_qkv, nullptr, 0L, nullptr, 0.f);

    // 3) v transpose -> vT[b][c][m]
    vtrans_k<<<dim3(32, 8, BATCH), 256>>>(qkT, vT);

    // 4) scores+exp+rowsum: E[n,m] = exp((1/16) sum_c q[n,c]*k[m,c])
    gemm_h<1><<<dim3(NPIX / 128, NPIX / 128, BATCH), 256>>>(
        qkT, qkT + CCH, E, CCH, 768, 768, NPIX,
        (long)NPIX * 768, (long)NPIX * 768, (long)NPIX * NPIX,
        nullptr, nullptr, 0L, rs, 0.0625f);

    // 5) AV + normalize: O[n,c] = (sum_m E[n,m]*vT[c,m]) / rowsum[n]
    gemm_h<2><<<dim3(CCH / 128, NPIX / 128, BATCH), 256>>>(
        E, vT, O, NPIX, NPIX, NPIX, CCH,
        (long)NPIX * NPIX, (long)CCH * NPIX, (long)NPIX * CCH,
        nullptr, nullptr, 0L, rs, 1.f);

    // 6) proj + bias + residual: out[o,pix] = sum_c Wp[o,c]*O[pix,c] + b[o] + x[o,pix]
    gemm_h<3><<<dim3(NPIX / 128, CCH / 128, BATCH), 256>>>(
        wp, O, out, CCH, CCH, CCH, NPIX,
        0L, (long)NPIX * CCH, (long)CCH * NPIX,
        b_proj, x, (long)CCH * NPIX, nullptr, 1.f);
}